// round 8
// baseline (speedup 1.0000x reference)
#include <cuda_runtime.h>
#include <cstdint>
#include <math.h>

#define NB 4
#define NN 512
#define NC 128

// logit scratch (4 MB)
__device__ float g_logits[NB * NN * NN];

// int8 quantized weights, hi/lo planes, permuted word layout.
// word counts per plane: L1 192*32=6144 | L2 192*48=9216 | L3 96*48=4608 | L4 96*24=2304
// layout: [L1 hi][L1 lo][L2 hi][L2 lo][L3 hi][L3 lo][L4 hi][L4 lo]
__device__ __align__(16) uint32_t g_w8[44544];
__device__ float g_dw[576];   // per-column dequant scales: L1[192] L2[192] L3[96] L4[96]

__device__ __forceinline__ float lrelu(float v) { return v > 0.f ? v : 0.01f * v; }
__device__ __forceinline__ int perm8(int p) { return (p & 3) * 2 + (p >> 2); }
__device__ __forceinline__ uint32_t smem_u32(const void* p) {
    uint32_t a;
    asm("{ .reg .u64 t; cvta.to.shared.u64 t, %1; cvt.u32.u64 %0, t; }" : "=r"(a) : "l"(p));
    return a;
}

// D(16x8,s32) += A(16x32,s8,row) * B(32x8,s8,col)
__device__ __forceinline__ void mmai8(int* d, uint32_t a0, uint32_t a1, uint32_t a2, uint32_t a3,
                                      uint32_t b0, uint32_t b1) {
    asm volatile("mma.sync.aligned.m16n8k32.row.col.s32.s8.s8.s32 "
                 "{%0,%1,%2,%3},{%4,%5,%6,%7},{%8,%9},{%0,%1,%2,%3};"
                 : "+r"(d[0]), "+r"(d[1]), "+r"(d[2]), "+r"(d[3])
                 : "r"(a0), "r"(a1), "r"(a2), "r"(a3), "r"(b0), "r"(b1));
}

#define CP_ASYNC16(dst_u32, src_ptr) \
    asm volatile("cp.async.cg.shared.global [%0], [%1], 16;" :: "r"(dst_u32), "l"(src_ptr) : "memory")
#define CP_COMMIT() asm volatile("cp.async.commit_group;" ::: "memory")
#define CP_WAIT0()  asm volatile("cp.async.wait_group 0;" ::: "memory")

__device__ __forceinline__ void quant(float v, float qA, int& h, int& l) {
    float ap = v * qA;
    h = __float2int_rn(ap);
    h = h > 127 ? 127 : (h < -127 ? -127 : h);
    int li = __float2int_rn((ap - (float)h) * 256.f);
    l = li > 127 ? 127 : (li < -127 ? -127 : li);
}

// One-time: quantize all 4 weight matrices to int8 hi/lo with per-column scales.
__global__ void convert_w8(const float* __restrict__ w1, const float* __restrict__ w2,
                           const float* __restrict__ w3, const float* __restrict__ w4)
{
    int gw = (blockIdx.x * blockDim.x + threadIdx.x) >> 5;
    int lane = threadIdx.x & 31;
    if (gw >= 576) return;
    const float* W; int K, n, base, planeW, dwoff;
    if (gw < 192)      { W = w1; K = 128; n = gw;       base = 0;     planeW = 6144; dwoff = 0; }
    else if (gw < 384) { W = w2; K = 192; n = gw - 192; base = 12288; planeW = 9216; dwoff = 192; }
    else if (gw < 480) { W = w3; K = 192; n = gw - 384; base = 30720; planeW = 4608; dwoff = 384; }
    else               { W = w4; K = 96;  n = gw - 480; base = 39936; planeW = 2304; dwoff = 480; }

    float mx = 1e-30f;
    for (int k = lane; k < K; k += 32) mx = fmaxf(mx, fabsf(W[n * K + k]));
#pragma unroll
    for (int o = 16; o; o >>= 1) mx = fmaxf(mx, __shfl_xor_sync(0xffffffffu, mx, o));
    float qW = 126.f / mx;
    if (lane == 0) g_dw[dwoff + n] = mx * (1.f / 126.f);

    for (int w = lane; w < K / 4; w += 32) {
        uint32_t hw = 0, lw = 0;
        for (int b = 0; b < 4; ++b) {
            int h, l;
            quant(W[n * K + 4 * w + b], qW, h, l);
            hw |= (uint32_t)(h & 255) << (8 * b);
            lw |= (uint32_t)(l & 255) << (8 * b);
        }
        int pos = base + n * (K / 4) + (w >> 3) * 8 + perm8(w & 7);
        g_w8[pos] = hw;
        g_w8[pos + planeW] = lw;
    }
}

// Stage one layer's weights (hi+lo planes) gmem -> smem via 16B cp.async.
__device__ __forceinline__ void stage_w(const uint32_t* __restrict__ gh, int planeW,
                                        int nN, int Ku, int SW_, uint32_t whb, uint32_t wlb, int tid)
{
    int total = nN * Ku;
    for (int idx = tid; idx < total; idx += 512) {
        int n = idx / Ku, uu = idx - n * Ku;
        int srcw = n * (Ku * 4) + uu * 4;
        uint32_t dst = (uint32_t)((n * SW_ + uu * 4) * 4);
        CP_ASYNC16(whb + dst, gh + srcw);
        CP_ASYNC16(wlb + dst, gh + planeW + srcw);
    }
    CP_COMMIT();
}

// One MLP layer, int8 3-term, in-place on A planes (strides SA -> SO, words).
// Warp grid 8m x 2n: mb=(wid&7)*16 (16 rows), n-half=(wid>>3)*(N/2), NPASS passes of 24 cols.
template <int N, int K, int SA, int SO, int NPASS, bool LAST>
__device__ void layerI8(uint32_t* __restrict__ AH, uint32_t* __restrict__ AL,
                        const uint32_t* __restrict__ WH, const uint32_t* __restrict__ WL,
                        int bOff, float& dA,
                        const uint32_t* __restrict__ nextG, int nextPW, int nextN, int nextKu, int nextSW,
                        uint32_t whb, uint32_t wlb,
                        float* __restrict__ sMax, float* __restrict__ srow,
                        const float* __restrict__ sDW, const float* __restrict__ sBias,
                        const float* __restrict__ sW5, int tid)
{
    constexpr int NCH = K / 32;
    const int wid = tid >> 5, lane = tid & 31;
    const int g = lane >> 2, t = lane & 3;
    const int mb = (wid & 7) * 16;
    const int nq = (wid >> 3) * (N / 2);

    float vf[NPASS * 12];
#pragma unroll
    for (int pass = 0; pass < NPASS; ++pass) {
        int ac0[3][4], ac1[3][4];
#pragma unroll
        for (int nt = 0; nt < 3; ++nt)
#pragma unroll
            for (int q = 0; q < 4; ++q) { ac0[nt][q] = 0; ac1[nt][q] = 0; }

        for (int c = 0; c < NCH; ++c) {
            int rb = (mb + g) * SA + c * 8 + 2 * t;
            uint2 h0 = *(const uint2*)(AH + rb), h1 = *(const uint2*)(AH + rb + 8 * SA);
            uint2 l0 = *(const uint2*)(AL + rb), l1 = *(const uint2*)(AL + rb + 8 * SA);
#pragma unroll
            for (int nt = 0; nt < 3; ++nt) {
                int n = nq + pass * 24 + nt * 8 + g;
                int wb = n * SA + c * 8 + 2 * t;
                uint2 bh = *(const uint2*)(WH + wb);
                uint2 bl = *(const uint2*)(WL + wb);
                mmai8(ac0[nt], h0.x, h1.x, h0.y, h1.y, bh.x, bh.y);
                mmai8(ac1[nt], l0.x, l1.x, l0.y, l1.y, bh.x, bh.y);
                mmai8(ac1[nt], h0.x, h1.x, h0.y, h1.y, bl.x, bl.y);
            }
        }
        // accs -> float, bias + lrelu
#pragma unroll
        for (int nt = 0; nt < 3; ++nt)
#pragma unroll
            for (int q = 0; q < 4; ++q) {
                int cb = nq + pass * 24 + nt * 8 + 2 * t + (q & 1);
                float accf = (float)ac0[nt][q] + (float)ac1[nt][q] * (1.f / 256.f);
                float v = accf * (dA * sDW[bOff + cb]) + sBias[bOff + cb];
                vf[pass * 12 + nt * 4 + q] = lrelu(v);
            }
    }
    __syncthreads();   // all A/W reads complete; A and W regions now writable

    if (!LAST) stage_w(nextG, nextPW, nextN, nextKu, nextSW, whb, wlb, tid);

    if (LAST) {
        float pr[2] = {0.f, 0.f};
#pragma unroll
        for (int pass = 0; pass < NPASS; ++pass)
#pragma unroll
            for (int nt = 0; nt < 3; ++nt)
#pragma unroll
                for (int q = 0; q < 4; ++q) {
                    int cb = nq + pass * 24 + nt * 8 + 2 * t + (q & 1);
                    pr[q >> 1] += vf[pass * 12 + nt * 4 + q] * sW5[cb];
                }
#pragma unroll
        for (int k = 0; k < 2; ++k) {
            pr[k] += __shfl_xor_sync(0xffffffffu, pr[k], 1);
            pr[k] += __shfl_xor_sync(0xffffffffu, pr[k], 2);
        }
        if (t == 0) {
            atomicAdd(&srow[mb + g], pr[0]);
            atomicAdd(&srow[mb + 8 + g], pr[1]);
        }
    } else {
        float mx = 0.f;
#pragma unroll
        for (int i = 0; i < NPASS * 12; ++i) mx = fmaxf(mx, fabsf(vf[i]));
#pragma unroll
        for (int o = 16; o; o >>= 1) mx = fmaxf(mx, __shfl_xor_sync(0xffffffffu, mx, o));
        if (lane == 0) sMax[wid] = mx;
        __syncthreads();
        mx = 1e-30f;
#pragma unroll
        for (int w = 0; w < 16; ++w) mx = fmaxf(mx, sMax[w]);
        float qA = 126.f / mx;
        dA = mx * (1.f / 126.f);
        // quantize + write u16 pairs into A planes (stride SO), permuted
#pragma unroll
        for (int pass = 0; pass < NPASS; ++pass)
#pragma unroll
            for (int rh = 0; rh < 2; ++rh) {
                int r = mb + rh * 8 + g;
#pragma unroll
                for (int nt = 0; nt < 3; ++nt) {
                    int cb = nq + pass * 24 + nt * 8 + 2 * t;
                    int h0, l0, h1, l1;
                    quant(vf[pass * 12 + nt * 4 + rh * 2 + 0], qA, h0, l0);
                    quant(vf[pass * 12 + nt * 4 + rh * 2 + 1], qA, h1, l1);
                    int word = (cb >> 5) * 8 + perm8((cb >> 2) & 7);
                    int off = (r * SO + word) * 4 + (cb & 3);
                    *(short*)((char*)AH + off) = (short)((h0 & 255) | ((h1 & 255) << 8));
                    *(short*)((char*)AL + off) = (short)((l0 & 255) | ((l1 & 255) << 8));
                }
            }
        CP_WAIT0();
        __syncthreads();
    }
}

extern __shared__ uint32_t dynsm[];

__global__ void __launch_bounds__(512, 1)
mlp_kernel(const float* __restrict__ x,
           const float* __restrict__ b1, const float* __restrict__ b2,
           const float* __restrict__ b3, const float* __restrict__ b4,
           const float* __restrict__ w5, const float* __restrict__ b5)
{
    __shared__ float sXi[NC];
    __shared__ float sBias[576];
    __shared__ float sDW[576];
    __shared__ float sW5[96];
    __shared__ float sB5;
    __shared__ float sMax[16];
    __shared__ float srow[128];

    const int tid = threadIdx.x;

    // block -> (b, i, jt) over symmetric 128-tiles
    int blk = blockIdx.x;
    int b = blk / 1280;
    int tt = blk - b * 1280;
    int ib, local, cnt;
    if (tt < 512)       { ib = 0; local = tt;        cnt = 4; }
    else if (tt < 896)  { ib = 1; local = tt - 512;  cnt = 3; }
    else if (tt < 1152) { ib = 2; local = tt - 896;  cnt = 2; }
    else                { ib = 3; local = tt - 1152; cnt = 1; }
    const int i  = ib * 128 + local / cnt;
    const int jt = ib + local % cnt;
    const int j0 = jt * 128;

    const float* xb = x + (size_t)b * NN * NC;

    uint32_t* AH = dynsm;                // 7168 words (128 x 56 max)
    uint32_t* AL = AH + 7168;
    uint32_t* WH = AH + 14336;           // 10752 words (192 x 56 max)
    uint32_t* WL = WH + 10752;
    const uint32_t whb = smem_u32(WH);
    const uint32_t wlb = smem_u32(WL);

    if (tid < 128) { sXi[tid] = xb[(size_t)i * NC + tid]; srow[tid] = 0.f; }
    if (tid < 192) { sBias[tid] = b1[tid]; sBias[192 + tid] = b2[tid]; }
    if (tid < 96)  { sBias[384 + tid] = b3[tid]; sBias[480 + tid] = b4[tid]; sW5[tid] = w5[tid]; }
    if (tid < 512 && tid >= 128 && tid < 128 + 576 - 128) {}
    for (int q = tid; q < 576; q += 512) sDW[q] = g_dw[q];
    if (tid == 0) sB5 = b5[0];
    __syncthreads();

    // stage L1 weights while computing the prologue
    stage_w(g_w8 + 0, 6144, 192, 8, 40, whb, wlb, tid);

    // prologue pass 1: d = |xi - xj|, find tile max  (thread: row r, col quarter q)
    const int r = tid >> 2, q = tid & 3;
    float dv[32];
    {
        const float* xr = xb + (size_t)(j0 + r) * NC + 32 * q;
        const float* xi = sXi + 32 * q;
        float mx = 1e-30f;
#pragma unroll
        for (int u = 0; u < 32; ++u) {
            dv[u] = fabsf(xi[u] - xr[u]);
            mx = fmaxf(mx, dv[u]);
        }
#pragma unroll
        for (int o = 16; o; o >>= 1) mx = fmaxf(mx, __shfl_xor_sync(0xffffffffu, mx, o));
        if ((tid & 31) == 0) sMax[tid >> 5] = mx;
    }
    __syncthreads();
    float dA;
    {
        float mx = 1e-30f;
#pragma unroll
        for (int w = 0; w < 16; ++w) mx = fmaxf(mx, sMax[w]);
        float qA = 126.f / mx;
        dA = mx * (1.f / 126.f);
        // pass 2: quantize, pack, store (stride 40 words, permuted)
#pragma unroll
        for (int p = 0; p < 8; ++p) {
            uint32_t hw = 0, lw = 0;
#pragma unroll
            for (int bb = 0; bb < 4; ++bb) {
                int h, l;
                quant(dv[4 * p + bb], qA, h, l);
                hw |= (uint32_t)(h & 255) << (8 * bb);
                lw |= (uint32_t)(l & 255) << (8 * bb);
            }
            int pos = r * 40 + q * 8 + perm8(p);
            AH[pos] = hw;
            AL[pos] = lw;
        }
    }
    CP_WAIT0();
    __syncthreads();

    layerI8<192, 128, 40, 56, 4, false>(AH, AL, WH, WL, 0, dA,
        g_w8 + 12288, 9216, 192, 12, 56, whb, wlb, sMax, srow, sDW, sBias, sW5, tid);
    layerI8<192, 192, 56, 56, 4, false>(AH, AL, WH, WL, 192, dA,
        g_w8 + 30720, 4608, 96, 12, 56, whb, wlb, sMax, srow, sDW, sBias, sW5, tid);
    layerI8<96, 192, 56, 24, 2, false>(AH, AL, WH, WL, 384, dA,
        g_w8 + 39936, 2304, 96, 6, 24, whb, wlb, sMax, srow, sDW, sBias, sW5, tid);
    layerI8<96, 96, 24, 24, 2, true>(AH, AL, WH, WL, 480, dA,
        g_w8, 0, 0, 1, 0, whb, wlb, sMax, srow, sDW, sBias, sW5, tid);
    __syncthreads();

    if (tid < 128) {
        float lg = srow[tid] + sB5;
        int j = j0 + tid;
        g_logits[((size_t)b * NN + i) * NN + j] = lg;   // direct
        g_logits[((size_t)b * NN + j) * NN + i] = lg;   // mirror (d symmetric)
    }
}

__global__ void __launch_bounds__(256)
softmax_kernel(float2* __restrict__ out)
{
    __shared__ float sred[8];
    __shared__ float sval;
    int row = blockIdx.x;
    int i   = row & (NN - 1);
    const float* L = g_logits + (size_t)row * NN;
    int tid  = threadIdx.x;
    int lane = tid & 31, warp = tid >> 5;

    float l0 = L[tid];
    float l1 = L[tid + 256];
    if (tid == i)       l0 -= 1e8f;
    if (tid + 256 == i) l1 -= 1e8f;

    float m = fmaxf(l0, l1);
#pragma unroll
    for (int o = 16; o > 0; o >>= 1) m = fmaxf(m, __shfl_xor_sync(0xffffffffu, m, o));
    if (lane == 0) sred[warp] = m;
    __syncthreads();
    if (tid == 0) {
        float v = sred[0];
        for (int w = 1; w < 8; ++w) v = fmaxf(v, sred[w]);
        sval = v;
    }
    __syncthreads();
    float M  = sval;
    float e0 = expf(l0 - M);
    float e1 = expf(l1 - M);
    float s  = e0 + e1;
#pragma unroll
    for (int o = 16; o > 0; o >>= 1) s += __shfl_xor_sync(0xffffffffu, s, o);
    __syncthreads();
    if (lane == 0) sred[warp] = s;
    __syncthreads();
    if (tid == 0) {
        float v = 0.f;
        for (int w = 0; w < 8; ++w) v += sred[w];
        sval = 1.0f / v;
    }
    __syncthreads();
    float inv = sval;

    float2* o2 = out + (size_t)row * NN;
    o2[tid]       = make_float2(tid == i ? 1.f : 0.f,       e0 * inv);
    o2[tid + 256] = make_float2(tid + 256 == i ? 1.f : 0.f, e1 * inv);
}

extern "C" void kernel_launch(void* const* d_in, const int* in_sizes, int n_in,
                              void* d_out, int out_size)
{
    const float* x  = (const float*)d_in[0];
    // d_in[1] = W_id (exact identity; regenerated analytically)
    const float* w1 = (const float*)d_in[2];
    const float* b1 = (const float*)d_in[3];
    const float* w2 = (const float*)d_in[4];
    const float* b2 = (const float*)d_in[5];
    const float* w3 = (const float*)d_in[6];
    const float* b3 = (const float*)d_in[7];
    const float* w4 = (const float*)d_in[8];
    const float* b4 = (const float*)d_in[9];
    const float* w5 = (const float*)d_in[10];
    const float* b5 = (const float*)d_in[11];
    float2* out = (float2*)d_out;

    // quantize weights (deterministic, graph-capturable, ~5 us)
    convert_w8<<<72, 256>>>(w1, w2, w3, w4);

    // dyn smem: A planes 2*7168 + W planes 2*10752 = 35840 words = 143,360 B
    size_t smem_bytes = 35840 * sizeof(uint32_t);
    cudaFuncSetAttribute(mlp_kernel, cudaFuncAttributeMaxDynamicSharedMemorySize,
                         (int)smem_bytes);

    mlp_kernel<<<NB * 1280, 512, smem_bytes>>>(x, b1, b2, b3, b4, w5, b5);
    softmax_kernel<<<NB * NN, 256>>>(out);
}

// round 9
// speedup vs baseline: 2.8402x; 2.8402x over previous
#include <cuda_runtime.h>
#include <cstdint>
#include <math.h>

#define NB 4
#define NN 512
#define NC 128

// logit scratch (4 MB)
__device__ float g_logits[NB * NN * NN];

__device__ __forceinline__ uint32_t f2tf32(float f) {
    uint32_t r;
    asm("cvt.rna.tf32.f32 %0, %1;" : "=r"(r) : "f"(f));
    return r;
}
__device__ __forceinline__ float lrelu(float v) { return v > 0.f ? v : 0.01f * v; }
__device__ __forceinline__ uint32_t smem_u32(const void* p) {
    uint32_t a;
    asm("{ .reg .u64 t; cvta.to.shared.u64 t, %1; cvt.u32.u64 %0, t; }" : "=r"(a) : "l"(p));
    return a;
}

// D(16x8,f32) += A(16x8,tf32,row) * B(8x8,tf32,col)
__device__ __forceinline__ void mma8(float* d, uint32_t a0, uint32_t a1, uint32_t a2, uint32_t a3,
                                     uint32_t b0, uint32_t b1) {
    asm volatile("mma.sync.aligned.m16n8k8.row.col.f32.tf32.tf32.f32 "
                 "{%0,%1,%2,%3},{%4,%5,%6,%7},{%8,%9},{%0,%1,%2,%3};"
                 : "+f"(d[0]), "+f"(d[1]), "+f"(d[2]), "+f"(d[3])
                 : "r"(a0), "r"(a1), "r"(a2), "r"(a3), "r"(b0), "r"(b1));
}

// permuted position of k within a 32-k chunk
__device__ __forceinline__ int perm32(int kk) { return (kk & 3) * 8 + (kk >> 2); }

#define CP_ASYNC4(dst_u32, src_ptr) \
    asm volatile("cp.async.ca.shared.global [%0], [%1], 4;" :: "r"(dst_u32), "l"(src_ptr) : "memory")
#define CP_COMMIT() asm volatile("cp.async.commit_group;" ::: "memory")
#define CP_WAIT0()  asm volatile("cp.async.wait_group 0;" ::: "memory")

// Stage one 32-k chunk of W[N][K] (src = &W[0][k0], row stride K) into SMEM
// (stride 36 words, permuted) via cp.async.
__device__ __forceinline__ void stage_chunk32(const float* __restrict__ src, int N, int K,
                                              uint32_t dstb, int tid) {
    int PW = N >> 4;
    for (int p = 0; p < PW; ++p) {
        int idx = tid + (p << 9);
        int n = idx >> 5, kk = idx & 31;
        CP_ASYNC4(dstb + (uint32_t)((n * 36 + perm32(kk)) * 4), src + n * K + kk);
    }
    CP_COMMIT();
}

// One MLP layer, in-place on `buf` (tf32 words; strides SA->SO, permuted k layout).
// On entry: this layer's chunk0 already committed (NOT waited) into sWa.
// On last chunk: stages NEXT layer's chunk0 into sWa (overlaps MMA + epilogue + boundary).
// 16 warps: warp_m = wid&3 (32 rows), warp_n = wid>>2 (N/4 cols).
template <int N, int K, int SA, int SO, int NEXTN, int NEXTK>
__device__ void layer(uint32_t* __restrict__ buf,
                      const float* __restrict__ Wg, const float* __restrict__ bias,
                      const float* __restrict__ nextWg,
                      uint32_t* __restrict__ sWa, uint32_t* __restrict__ sWb,
                      uint32_t swa_bytes, uint32_t swb_bytes, int tid)
{
    constexpr int NT  = N / 32;     // 8-wide n-tiles per warp
    constexpr int NCH = K / 32;     // 32-k chunks  (4, 6, 6, 3 — even where a next layer exists)

    const int wid = tid >> 5, lane = tid & 31;
    const int g = lane >> 2, t = lane & 3;
    const int mb  = (wid & 3) * 32;
    const int nwb = (wid >> 2) * (N / 4);

    // entry: wait for chunk0 (committed by prev layer / prologue) + order A writes
    CP_WAIT0();
    __syncthreads();

    float d[2][NT][4];
#pragma unroll
    for (int mt = 0; mt < 2; ++mt)
#pragma unroll
        for (int nt = 0; nt < NT; ++nt)
#pragma unroll
            for (int q = 0; q < 4; ++q) d[mt][nt][q] = 0.f;

    for (int c = 0; c < NCH; ++c) {
        if (c + 1 < NCH) {
            stage_chunk32(Wg + (c + 1) * 32, N, K,
                          ((c + 1) & 1) ? swb_bytes : swa_bytes, tid);
        } else if (NEXTN > 0) {
            // last chunk reads sWb (NCH even) -> chunk0 of next layer lands in sWa
            stage_chunk32(nextWg, NEXTN, NEXTK, swa_bytes, tid);
        }
        const uint32_t* sWc = (c & 1) ? sWb : sWa;
#pragma unroll
        for (int h = 0; h < 2; ++h) {
            uint32_t bf[NT][4];
#pragma unroll
            for (int nt = 0; nt < NT; ++nt) {
                int n = nwb + nt * 8 + g;
                *(uint4*)bf[nt] = *(const uint4*)(sWc + n * 36 + t * 8 + 4 * h);
            }
            uint32_t av[2][2][4];
#pragma unroll
            for (int mt = 0; mt < 2; ++mt) {
                int r0 = mb + mt * 16 + g;
                *(uint4*)av[mt][0] = *(const uint4*)(buf + r0 * SA + c * 32 + t * 8 + 4 * h);
                *(uint4*)av[mt][1] = *(const uint4*)(buf + (r0 + 8) * SA + c * 32 + t * 8 + 4 * h);
            }
#pragma unroll
            for (int ks = 0; ks < 2; ++ks)
#pragma unroll
                for (int mt = 0; mt < 2; ++mt)
#pragma unroll
                    for (int nt = 0; nt < NT; ++nt)
                        mma8(d[mt][nt],
                             av[mt][0][2 * ks], av[mt][1][2 * ks],
                             av[mt][0][2 * ks + 1], av[mt][1][2 * ks + 1],
                             bf[nt][2 * ks], bf[nt][2 * ks + 1]);
        }
        if (c + 1 < NCH) CP_WAIT0();
        __syncthreads();
    }

    // epilogue: bias + lrelu + tf32, in place (inputs dead after last sync), permuted
#pragma unroll
    for (int mt = 0; mt < 2; ++mt) {
        int r0 = mb + mt * 16 + g;
#pragma unroll
        for (int nt = 0; nt < NT; ++nt) {
            int cb = nwb + nt * 8 + 2 * t;
            float bb0 = bias[cb], bb1 = bias[cb + 1];
            int w0 = (cb >> 5) * 32 + perm32(cb & 31);
            int w1 = ((cb + 1) >> 5) * 32 + perm32((cb + 1) & 31);
            buf[r0 * SO + w0]       = f2tf32(lrelu(d[mt][nt][0] + bb0));
            buf[r0 * SO + w1]       = f2tf32(lrelu(d[mt][nt][1] + bb1));
            buf[(r0 + 8) * SO + w0] = f2tf32(lrelu(d[mt][nt][2] + bb0));
            buf[(r0 + 8) * SO + w1] = f2tf32(lrelu(d[mt][nt][3] + bb1));
        }
    }
    // next layer's entry wait+sync orders the epilogue writes
}

extern __shared__ uint32_t dynsm[];

__global__ void __launch_bounds__(512, 1)
mlp_kernel(const float* __restrict__ x,
           const float* __restrict__ w1, const float* __restrict__ b1,
           const float* __restrict__ w2, const float* __restrict__ b2,
           const float* __restrict__ w3, const float* __restrict__ b3,
           const float* __restrict__ w4, const float* __restrict__ b4,
           const float* __restrict__ w5, const float* __restrict__ b5)
{
    __shared__ float sXi[NC];
    __shared__ float sBias[576];
    __shared__ float sW5[96];
    __shared__ float sB5;

    const int tid = threadIdx.x;

    // block -> (b, i, jt) over symmetric 128-tiles: jt >= block(i)
    int blk = blockIdx.x;
    int b = blk / 1280;
    int t = blk - b * 1280;
    int ib, local, cnt;
    if (t < 512)       { ib = 0; local = t;        cnt = 4; }
    else if (t < 896)  { ib = 1; local = t - 512;  cnt = 3; }
    else if (t < 1152) { ib = 2; local = t - 896;  cnt = 2; }
    else               { ib = 3; local = t - 1152; cnt = 1; }
    const int i  = ib * 128 + local / cnt;
    const int jt = ib + local % cnt;
    const int j0 = jt * 128;

    const float* xb = x + (size_t)b * NN * NC;

    uint32_t* buf = dynsm;                 // 128*196 words, in-place across layers
    uint32_t* sWa = buf + 128 * 196;       // 192*36 words
    uint32_t* sWb = sWa + 192 * 36;
    const uint32_t swa_bytes = smem_u32(sWa);
    const uint32_t swb_bytes = smem_u32(sWb);

    if (tid < 128) sXi[tid] = xb[(size_t)i * NC + tid];
    if (tid < 192) { sBias[tid] = b1[tid]; sBias[192 + tid] = b2[tid]; }
    if (tid < 96)  { sBias[384 + tid] = b3[tid]; sBias[480 + tid] = b4[tid]; sW5[tid] = w5[tid]; }
    if (tid == 0)  sB5 = b5[0];

    // stage w1 chunk0 immediately (overlaps xi staging + prologue)
    stage_chunk32(w1, 192, 128, swa_bytes, tid);
    __syncthreads();   // sXi ready

    // prologue: buf[r][k] = tf32(|x_i[k] - x_{j0+r}[k]|), stride 132, permuted; float4 loads
    for (int idx = tid; idx < 128 * 32; idx += 512) {
        int r = idx >> 5, kq = idx & 31;
        float4 xj4 = *(const float4*)(xb + (size_t)(j0 + r) * NC + 4 * kq);
        float4 xi4 = *(const float4*)(sXi + 4 * kq);
        uint32_t* dst = buf + r * 132 + (kq >> 3) * 32 + (kq & 7);
        dst[0]  = f2tf32(fabsf(xi4.x - xj4.x));
        dst[8]  = f2tf32(fabsf(xi4.y - xj4.y));
        dst[16] = f2tf32(fabsf(xi4.z - xj4.z));
        dst[24] = f2tf32(fabsf(xi4.w - xj4.w));
    }
    // layer entry performs CP_WAIT0 + __syncthreads (orders prologue writes too)

    layer<192, 128, 132, 196, 192, 192>(buf, w1, sBias + 0,   w2, sWa, sWb, swa_bytes, swb_bytes, tid);
    layer<192, 192, 196, 196,  96, 192>(buf, w2, sBias + 192, w3, sWa, sWb, swa_bytes, swb_bytes, tid);
    layer< 96, 192, 196, 100,  96,  96>(buf, w3, sBias + 384, w4, sWa, sWb, swa_bytes, swb_bytes, tid);
    layer< 96,  96, 100, 100,   0,   0>(buf, w4, sBias + 480, (const float*)0, sWa, sWb, swa_bytes, swb_bytes, tid);
    __syncthreads();   // layer-4 epilogue visible

    // layer 5: 96 -> 1 (no activation); 4 threads per row, permuted reads
    {
        const int r = tid >> 2, q = tid & 3;
        const uint32_t* arow = buf + r * 100;
        float acc = 0.f;
#pragma unroll
        for (int k = 0; k < 24; ++k) {
            int col = q * 24 + k;
            int w = (col >> 5) * 32 + perm32(col & 31);
            acc = fmaf(__uint_as_float(arow[w]), sW5[col], acc);
        }
        acc += __shfl_xor_sync(0xffffffffu, acc, 1);
        acc += __shfl_xor_sync(0xffffffffu, acc, 2);
        if (q == 0) {
            float lg = acc + sB5;
            int j = j0 + r;
            g_logits[((size_t)b * NN + i) * NN + j] = lg;   // direct
            g_logits[((size_t)b * NN + j) * NN + i] = lg;   // mirror (d symmetric)
        }
    }
}

__global__ void __launch_bounds__(256)
softmax_kernel(float2* __restrict__ out)
{
    __shared__ float sred[8];
    __shared__ float sval;
    int row = blockIdx.x;
    int i   = row & (NN - 1);
    const float* L = g_logits + (size_t)row * NN;
    int tid  = threadIdx.x;
    int lane = tid & 31, warp = tid >> 5;

    float l0 = L[tid];
    float l1 = L[tid + 256];
    if (tid == i)       l0 -= 1e8f;
    if (tid + 256 == i) l1 -= 1e8f;

    float m = fmaxf(l0, l1);
#pragma unroll
    for (int o = 16; o > 0; o >>= 1) m = fmaxf(m, __shfl_xor_sync(0xffffffffu, m, o));
    if (lane == 0) sred[warp] = m;
    __syncthreads();
    if (tid == 0) {
        float v = sred[0];
        for (int w = 1; w < 8; ++w) v = fmaxf(v, sred[w]);
        sval = v;
    }
    __syncthreads();
    float M  = sval;
    float e0 = expf(l0 - M);
    float e1 = expf(l1 - M);
    float s  = e0 + e1;
#pragma unroll
    for (int o = 16; o > 0; o >>= 1) s += __shfl_xor_sync(0xffffffffu, s, o);
    __syncthreads();
    if (lane == 0) sred[warp] = s;
    __syncthreads();
    if (tid == 0) {
        float v = 0.f;
        for (int w = 0; w < 8; ++w) v += sred[w];
        sval = 1.0f / v;
    }
    __syncthreads();
    float inv = sval;

    float2* o2 = out + (size_t)row * NN;
    o2[tid]       = make_float2(tid == i ? 1.f : 0.f,       e0 * inv);
    o2[tid + 256] = make_float2(tid + 256 == i ? 1.f : 0.f, e1 * inv);
}

extern "C" void kernel_launch(void* const* d_in, const int* in_sizes, int n_in,
                              void* d_out, int out_size)
{
    const float* x  = (const float*)d_in[0];
    // d_in[1] = W_id (exact identity; regenerated analytically)
    const float* w1 = (const float*)d_in[2];
    const float* b1 = (const float*)d_in[3];
    const float* w2 = (const float*)d_in[4];
    const float* b2 = (const float*)d_in[5];
    const float* w3 = (const float*)d_in[6];
    const float* b3 = (const float*)d_in[7];
    const float* w4 = (const float*)d_in[8];
    const float* b4 = (const float*)d_in[9];
    const float* w5 = (const float*)d_in[10];
    const float* b5 = (const float*)d_in[11];
    float2* out = (float2*)d_out;

    // dyn smem: act buf 128x196 + 2 weight chunk buffers 192x36 = 155,648 B
    size_t smem_bytes = (128 * 196 + 2 * 192 * 36) * sizeof(uint32_t);
    cudaFuncSetAttribute(mlp_kernel, cudaFuncAttributeMaxDynamicSharedMemorySize,
                         (int)smem_bytes);

    mlp_kernel<<<NB * 1280, 512, smem_bytes>>>(
        x, w1, b1, w2, b2, w3, b3, w4, b4, w5, b5);
    softmax_kernel<<<NB * NN, 256>>>(out);
}

// round 10
// speedup vs baseline: 3.5353x; 1.2447x over previous
#include <cuda_runtime.h>
#include <cstdint>
#include <math.h>

#define NB 4
#define NN 512
#define NC 128

// logit scratch (4 MB). Diagonal entries never written; softmax masks them exactly.
__device__ float g_logits[NB * NN * NN];

__device__ __forceinline__ uint32_t f2tf32(float f) {
    uint32_t r;
    asm("cvt.rna.tf32.f32 %0, %1;" : "=r"(r) : "f"(f));
    return r;
}
__device__ __forceinline__ float lrelu(float v) { return v > 0.f ? v : 0.01f * v; }
__device__ __forceinline__ uint32_t smem_u32(const void* p) {
    uint32_t a;
    asm("{ .reg .u64 t; cvta.to.shared.u64 t, %1; cvt.u32.u64 %0, t; }" : "=r"(a) : "l"(p));
    return a;
}

// D(16x8,f32) += A(16x8,tf32,row) * B(8x8,tf32,col)
__device__ __forceinline__ void mma8(float* d, uint32_t a0, uint32_t a1, uint32_t a2, uint32_t a3,
                                     uint32_t b0, uint32_t b1) {
    asm volatile("mma.sync.aligned.m16n8k8.row.col.f32.tf32.tf32.f32 "
                 "{%0,%1,%2,%3},{%4,%5,%6,%7},{%8,%9},{%0,%1,%2,%3};"
                 : "+f"(d[0]), "+f"(d[1]), "+f"(d[2]), "+f"(d[3])
                 : "r"(a0), "r"(a1), "r"(a2), "r"(a3), "r"(b0), "r"(b1));
}

// permuted position of k within a 32-k chunk
__device__ __forceinline__ int perm32(int kk) { return (kk & 3) * 8 + (kk >> 2); }

#define CP_ASYNC4(dst_u32, src_ptr) \
    asm volatile("cp.async.ca.shared.global [%0], [%1], 4;" :: "r"(dst_u32), "l"(src_ptr) : "memory")
#define CP_COMMIT() asm volatile("cp.async.commit_group;" ::: "memory")
#define CP_WAIT0()  asm volatile("cp.async.wait_group 0;" ::: "memory")

// Stage one 32-k chunk of W[N][K] (src = &W[0][k0], row stride K) into SMEM
// (stride 36 words, permuted) via cp.async.
__device__ __forceinline__ void stage_chunk32(const float* __restrict__ src, int N, int K,
                                              uint32_t dstb, int tid) {
    int PW = N >> 4;
    for (int p = 0; p < PW; ++p) {
        int idx = tid + (p << 9);
        int n = idx >> 5, kk = idx & 31;
        CP_ASYNC4(dstb + (uint32_t)((n * 36 + perm32(kk)) * 4), src + n * K + kk);
    }
    CP_COMMIT();
}

// One MLP layer, in-place on `buf` (tf32 words; strides SA->SO, permuted k layout).
// On entry: this layer's chunk0 already committed (NOT waited) into sWa.
// On last chunk: stages NEXT layer's chunk0 into sWa (overlaps MMA + epilogue + boundary).
// 16 warps: warp_m = wid&3 (32 rows), warp_n = wid>>2 (N/4 cols).
template <int N, int K, int SA, int SO, int NEXTN, int NEXTK>
__device__ void layer(uint32_t* __restrict__ buf,
                      const float* __restrict__ Wg, const float* __restrict__ bias,
                      const float* __restrict__ nextWg,
                      uint32_t* __restrict__ sWa, uint32_t* __restrict__ sWb,
                      uint32_t swa_bytes, uint32_t swb_bytes, int tid)
{
    constexpr int NT  = N / 32;     // 8-wide n-tiles per warp
    constexpr int NCH = K / 32;     // 32-k chunks  (4, 6, 6, 3 — even where a next layer exists)

    const int wid = tid >> 5, lane = tid & 31;
    const int g = lane >> 2, t = lane & 3;
    const int mb  = (wid & 3) * 32;
    const int nwb = (wid >> 2) * (N / 4);

    // entry: wait for chunk0 (committed by prev layer / prologue) + order A writes
    CP_WAIT0();
    __syncthreads();

    float d[2][NT][4];
#pragma unroll
    for (int mt = 0; mt < 2; ++mt)
#pragma unroll
        for (int nt = 0; nt < NT; ++nt)
#pragma unroll
            for (int q = 0; q < 4; ++q) d[mt][nt][q] = 0.f;

    for (int c = 0; c < NCH; ++c) {
        if (c + 1 < NCH) {
            stage_chunk32(Wg + (c + 1) * 32, N, K,
                          ((c + 1) & 1) ? swb_bytes : swa_bytes, tid);
        } else if (NEXTN > 0) {
            // last chunk reads sWb (NCH even) -> chunk0 of next layer lands in sWa
            stage_chunk32(nextWg, NEXTN, NEXTK, swa_bytes, tid);
        }
        const uint32_t* sWc = (c & 1) ? sWb : sWa;
#pragma unroll
        for (int h = 0; h < 2; ++h) {
            uint32_t bf[NT][4];
#pragma unroll
            for (int nt = 0; nt < NT; ++nt) {
                int n = nwb + nt * 8 + g;
                *(uint4*)bf[nt] = *(const uint4*)(sWc + n * 36 + t * 8 + 4 * h);
            }
            uint32_t av[2][2][4];
#pragma unroll
            for (int mt = 0; mt < 2; ++mt) {
                int r0 = mb + mt * 16 + g;
                *(uint4*)av[mt][0] = *(const uint4*)(buf + r0 * SA + c * 32 + t * 8 + 4 * h);
                *(uint4*)av[mt][1] = *(const uint4*)(buf + (r0 + 8) * SA + c * 32 + t * 8 + 4 * h);
            }
#pragma unroll
            for (int ks = 0; ks < 2; ++ks)
#pragma unroll
                for (int mt = 0; mt < 2; ++mt)
#pragma unroll
                    for (int nt = 0; nt < NT; ++nt)
                        mma8(d[mt][nt],
                             av[mt][0][2 * ks], av[mt][1][2 * ks],
                             av[mt][0][2 * ks + 1], av[mt][1][2 * ks + 1],
                             bf[nt][2 * ks], bf[nt][2 * ks + 1]);
        }
        if (c + 1 < NCH) CP_WAIT0();
        __syncthreads();
    }

    // epilogue: bias + lrelu + tf32, in place (inputs dead after last sync), permuted
#pragma unroll
    for (int mt = 0; mt < 2; ++mt) {
        int r0 = mb + mt * 16 + g;
#pragma unroll
        for (int nt = 0; nt < NT; ++nt) {
            int cb = nwb + nt * 8 + 2 * t;
            float bb0 = bias[cb], bb1 = bias[cb + 1];
            int w0 = (cb >> 5) * 32 + perm32(cb & 31);
            int w1 = ((cb + 1) >> 5) * 32 + perm32((cb + 1) & 31);
            buf[r0 * SO + w0]       = f2tf32(lrelu(d[mt][nt][0] + bb0));
            buf[r0 * SO + w1]       = f2tf32(lrelu(d[mt][nt][1] + bb1));
            buf[(r0 + 8) * SO + w0] = f2tf32(lrelu(d[mt][nt][2] + bb0));
            buf[(r0 + 8) * SO + w1] = f2tf32(lrelu(d[mt][nt][3] + bb1));
        }
    }
    // next layer's entry wait+sync orders the epilogue writes
}

extern __shared__ uint32_t dynsm[];

__global__ void __launch_bounds__(512, 1)
mlp_kernel(const float* __restrict__ x,
           const float* __restrict__ w1, const float* __restrict__ b1,
           const float* __restrict__ w2, const float* __restrict__ b2,
           const float* __restrict__ w3, const float* __restrict__ b3,
           const float* __restrict__ w4, const float* __restrict__ b4,
           const float* __restrict__ w5, const float* __restrict__ b5)
{
    __shared__ float sXi[256];     // [0:128) = x[I0], [128:256) = x[I1]
    __shared__ float sBias[576];
    __shared__ float sW5[96];
    __shared__ float sB5;

    const int tid = threadIdx.x;

    // ---- exact-dedup tile decode: 1024 CTAs per batch ----
    // t <  768: off-diagonal (single i, full 128-j block, jt > ib)
    // t >= 768: diagonal block row-pair CTA: edges (i1=base+p, j>i1) + (i2=base+127-p, j>i2)
    const int blk = blockIdx.x;
    const int b = blk >> 10;
    const int t = blk & 1023;
    int I0, I1, rsplit, jbase, pp = 0;
    bool isDiag = false;
    if (t < 384)      { I0 = t / 3;              jbase = 128 * (1 + t % 3); }
    else if (t < 640) { int l = t - 384; I0 = 128 + (l >> 1); jbase = 128 * (2 + (l & 1)); }
    else if (t < 768) { I0 = 256 + (t - 640);    jbase = 384; }
    else {
        isDiag = true;
        int dd = t - 768;
        int ibd = dd >> 6;
        pp = dd & 63;
        jbase = ibd * 128;
        I0 = jbase + pp;
        I1 = jbase + 127 - pp;
    }
    if (!isDiag) { I1 = I0; rsplit = 128; }
    else rsplit = 127 - pp;

    const float* xb = x + (size_t)b * NN * NC;

    uint32_t* buf = dynsm;                 // 128*196 words, in-place across layers
    uint32_t* sWa = buf + 128 * 196;       // 192*36 words
    uint32_t* sWb = sWa + 192 * 36;
    const uint32_t swa_bytes = smem_u32(sWa);
    const uint32_t swb_bytes = smem_u32(sWb);

    if (tid < 128)      sXi[tid] = xb[(size_t)I0 * NC + tid];
    else if (tid < 256) sXi[tid] = xb[(size_t)I1 * NC + (tid - 128)];
    if (tid < 192) { sBias[tid] = b1[tid]; sBias[192 + tid] = b2[tid]; }
    if (tid < 96)  { sBias[384 + tid] = b3[tid]; sBias[480 + tid] = b4[tid]; sW5[tid] = w5[tid]; }
    if (tid == 0)  sB5 = b5[0];

    // stage w1 chunk0 immediately (overlaps xi staging + prologue)
    stage_chunk32(w1, 192, 128, swa_bytes, tid);
    __syncthreads();   // sXi ready

    // prologue: buf[r][k] = tf32(|x_I(r)[k] - x_J(r)[k]|), stride 132, permuted; float4 loads
    for (int idx = tid; idx < 128 * 32; idx += 512) {
        int r = idx >> 5, kq = idx & 31;
        int J;
        if (isDiag) J = (r == 127) ? jbase : (jbase + 1 + r + ((r < rsplit) ? pp : 0));
        else        J = jbase + r;
        const float* xi = sXi + ((r < rsplit) ? 0 : 128);
        float4 xj4 = *(const float4*)(xb + (size_t)J * NC + 4 * kq);
        float4 xi4 = *(const float4*)(xi + 4 * kq);
        uint32_t* dst = buf + r * 132 + (kq >> 3) * 32 + (kq & 7);
        dst[0]  = f2tf32(fabsf(xi4.x - xj4.x));
        dst[8]  = f2tf32(fabsf(xi4.y - xj4.y));
        dst[16] = f2tf32(fabsf(xi4.z - xj4.z));
        dst[24] = f2tf32(fabsf(xi4.w - xj4.w));
    }
    // layer entry performs CP_WAIT0 + __syncthreads (orders prologue writes too)

    layer<192, 128, 132, 196, 192, 192>(buf, w1, sBias + 0,   w2, sWa, sWb, swa_bytes, swb_bytes, tid);
    layer<192, 192, 196, 196,  96, 192>(buf, w2, sBias + 192, w3, sWa, sWb, swa_bytes, swb_bytes, tid);
    layer< 96, 192, 196, 100,  96,  96>(buf, w3, sBias + 384, w4, sWa, sWb, swa_bytes, swb_bytes, tid);
    layer< 96,  96, 100, 100,   0,   0>(buf, w4, sBias + 480, (const float*)0, sWa, sWb, swa_bytes, swb_bytes, tid);
    __syncthreads();   // layer-4 epilogue visible

    // layer 5: 96 -> 1 (no activation); 4 threads per row, permuted reads
    {
        const int r = tid >> 2, q = tid & 3;
        const uint32_t* arow = buf + r * 100;
        float acc = 0.f;
#pragma unroll
        for (int k = 0; k < 24; ++k) {
            int col = q * 24 + k;
            int w = (col >> 5) * 32 + perm32(col & 31);
            acc = fmaf(__uint_as_float(arow[w]), sW5[col], acc);
        }
        acc += __shfl_xor_sync(0xffffffffu, acc, 1);
        acc += __shfl_xor_sync(0xffffffffu, acc, 2);
        if (q == 0 && !(isDiag && r == 127)) {
            float lg = acc + sB5;
            int I = (r < rsplit) ? I0 : I1;
            int J;
            if (isDiag) J = jbase + 1 + r + ((r < rsplit) ? pp : 0);
            else        J = jbase + r;
            g_logits[((size_t)b * NN + I) * NN + J] = lg;   // direct
            g_logits[((size_t)b * NN + J) * NN + I] = lg;   // mirror (d symmetric)
        }
    }
}

__global__ void __launch_bounds__(256)
softmax_kernel(float2* __restrict__ out)
{
    __shared__ float sred[8];
    __shared__ float sval;
    int row = blockIdx.x;
    int i   = row & (NN - 1);
    const float* L = g_logits + (size_t)row * NN;
    int tid  = threadIdx.x;
    int lane = tid & 31, warp = tid >> 5;

    // self-edge masked exactly (diagonal logits are never computed)
    float l0 = (tid == i)       ? -1e8f : L[tid];
    float l1 = (tid + 256 == i) ? -1e8f : L[tid + 256];

    float m = fmaxf(l0, l1);
#pragma unroll
    for (int o = 16; o > 0; o >>= 1) m = fmaxf(m, __shfl_xor_sync(0xffffffffu, m, o));
    if (lane == 0) sred[warp] = m;
    __syncthreads();
    if (tid == 0) {
        float v = sred[0];
        for (int w = 1; w < 8; ++w) v = fmaxf(v, sred[w]);
        sval = v;
    }
    __syncthreads();
    float M  = sval;
    float e0 = expf(l0 - M);
    float e1 = expf(l1 - M);
    float s  = e0 + e1;
#pragma unroll
    for (int o = 16; o > 0; o >>= 1) s += __shfl_xor_sync(0xffffffffu, s, o);
    __syncthreads();
    if (lane == 0) sred[warp] = s;
    __syncthreads();
    if (tid == 0) {
        float v = 0.f;
        for (int w = 0; w < 8; ++w) v += sred[w];
        sval = 1.0f / v;
    }
    __syncthreads();
    float inv = sval;

    float2* o2 = out + (size_t)row * NN;
    o2[tid]       = make_float2(tid == i ? 1.f : 0.f,       e0 * inv);
    o2[tid + 256] = make_float2(tid + 256 == i ? 1.f : 0.f, e1 * inv);
}

extern "C" void kernel_launch(void* const* d_in, const int* in_sizes, int n_in,
                              void* d_out, int out_size)
{
    const float* x  = (const float*)d_in[0];
    // d_in[1] = W_id (exact identity; regenerated analytically)
    const float* w1 = (const float*)d_in[2];
    const float* b1 = (const float*)d_in[3];
    const float* w2 = (const float*)d_in[4];
    const float* b2 = (const float*)d_in[5];
    const float* w3 = (const float*)d_in[6];
    const float* b3 = (const float*)d_in[7];
    const float* w4 = (const float*)d_in[8];
    const float* b4 = (const float*)d_in[9];
    const float* w5 = (const float*)d_in[10];
    const float* b5 = (const float*)d_in[11];
    float2* out = (float2*)d_out;

    // dyn smem: act buf 128x196 + 2 weight chunk buffers 192x36 = 155,648 B
    size_t smem_bytes = (128 * 196 + 2 * 192 * 36) * sizeof(uint32_t);
    cudaFuncSetAttribute(mlp_kernel, cudaFuncAttributeMaxDynamicSharedMemorySize,
                         (int)smem_bytes);

    // exact-dedup tile set: 4 batches x 1024 CTAs
    mlp_kernel<<<NB * 1024, 512, smem_bytes>>>(
        x, w1, b1, w2, b2, w3, b3, w4, b4, w5, b5);
    softmax_kernel<<<NB * NN, 256>>>(out);
}